// round 9
// baseline (speedup 1.0000x reference)
#include <cuda_runtime.h>
#include <cuda_bf16.h>
#include <cstdint>

// ----------------------------------------------------------------------------
// Problem constants
// ----------------------------------------------------------------------------
#define BATCH     64
#define L_SEQ     256
#define IN_IMG    512
#define IN_PC     256
#define COMB      770
#define DIM       128
#define D_MODEL   1282
#define D_INNER   2564
#define D_STATE   16
#define D_CONV    4
#define DT_RANK   81
#define XPROJ_N   113
#define XPROJ_LD  116            // padded leading dim of g_dbl (even, 8B rows)
#define M_TOTAL   (BATCH * L_SEQ)      // 16384

#define POOL5_OFF   0
#define POOL9_OFF   1600
#define POOL13_OFF  6784
#define POOL_ROWS   17600

// ----------------------------------------------------------------------------
// Device scratch (static — proven set; g_dbl padded to XPROJ_LD)
// ----------------------------------------------------------------------------
__device__ __align__(16) float g_seq   [(size_t)M_TOTAL * D_MODEL];
__device__ __align__(16) float g_comb  [(size_t)BATCH * COMB * L_SEQ];
__device__ __align__(16) float g_xz    [(size_t)M_TOTAL * 2 * D_INNER];
__device__ __align__(16) float g_uact  [(size_t)M_TOTAL * D_INNER];
__device__ __align__(16) float g_dbl   [(size_t)M_TOTAL * XPROJ_LD];
__device__ __align__(16) float g_dt    [(size_t)M_TOTAL * D_INNER];
__device__ __align__(16) float g_y     [(size_t)M_TOTAL * D_INNER];
__device__ __align__(16) float g_p0    [(size_t)M_TOTAL * DIM];
__device__ __align__(16) float g_y0    [BATCH * DIM];
__device__ __align__(16) float g_pooled[(size_t)POOL_ROWS * COMB];
__device__ __align__(16) float g_ys    [(size_t)POOL_ROWS * DIM];
__device__ __align__(16) float g_bninv [4 * DIM];
__device__ __align__(16) float g_bnbias[4 * DIM];

// ----------------------------------------------------------------------------
// PTX helpers (baseline-ISA only: ldmatrix + mma.sync)
// ----------------------------------------------------------------------------
__device__ __forceinline__ uint32_t smem_to_u32(const void* p) {
    uint32_t a;
    asm("{ .reg .u64 t; cvta.to.shared.u64 t, %1; cvt.u32.u64 %0, t; }"
        : "=r"(a) : "l"(p));
    return a;
}
__device__ __forceinline__ void ldsm4(uint32_t* f, uint32_t addr) {
    asm volatile("ldmatrix.sync.aligned.m8n8.x4.shared.b16 {%0,%1,%2,%3}, [%4];"
                 : "=r"(f[0]), "=r"(f[1]), "=r"(f[2]), "=r"(f[3]) : "r"(addr));
}
__device__ __forceinline__ void mma16816(float* d, const uint32_t* a,
                                         uint32_t b0, uint32_t b1) {
    asm volatile(
        "mma.sync.aligned.m16n8k16.row.col.f32.bf16.bf16.f32 "
        "{%0,%1,%2,%3}, {%4,%5,%6,%7}, {%8,%9}, {%0,%1,%2,%3};"
        : "+f"(d[0]), "+f"(d[1]), "+f"(d[2]), "+f"(d[3])
        : "r"(a[0]), "r"(a[1]), "r"(a[2]), "r"(a[3]), "r"(b0), "r"(b1));
}

// fp32[8] -> bf16 hi uint4 + bf16 lo uint4
__device__ __forceinline__ void cvt_hilo(const float* v, uint4& hi, uint4& lo) {
    uint32_t h[4], l[4];
    #pragma unroll
    for (int i = 0; i < 4; i++) {
        __nv_bfloat16 h0 = __float2bfloat16(v[2*i]);
        __nv_bfloat16 h1 = __float2bfloat16(v[2*i+1]);
        float r0 = v[2*i]   - __bfloat162float(h0);
        float r1 = v[2*i+1] - __bfloat162float(h1);
        __nv_bfloat16 l0 = __float2bfloat16(r0);
        __nv_bfloat16 l1 = __float2bfloat16(r1);
        h[i] = (uint32_t)__bfloat16_as_ushort(h0) | ((uint32_t)__bfloat16_as_ushort(h1) << 16);
        l[i] = (uint32_t)__bfloat16_as_ushort(l0) | ((uint32_t)__bfloat16_as_ushort(l1) << 16);
    }
    hi = make_uint4(h[0], h[1], h[2], h[3]);
    lo = make_uint4(l[0], l[1], l[2], l[3]);
}

// 8-float unit load: vectorized float2 x4 fast path when the unit is fully
// in-bounds and rows are 8B-aligned (even lda); guarded scalar path otherwise.
__device__ __forceinline__ void load_unit(const float* p, bool rowok, int krem,
                                          bool al8, float* v) {
    if (rowok && al8 && krem >= 8) {
        const float2* q = (const float2*)p;
        float2 a = q[0], b = q[1], c = q[2], d = q[3];
        v[0] = a.x; v[1] = a.y; v[2] = b.x; v[3] = b.y;
        v[4] = c.x; v[5] = c.y; v[6] = d.x; v[7] = d.y;
    } else {
        #pragma unroll
        for (int i = 0; i < 8; i++)
            v[i] = (rowok && i < krem) ? p[i] : 0.f;
    }
}

// ----------------------------------------------------------------------------
// HMMA bf16x3-split GEMM, in-register split, register-prefetch pipeline,
// vectorized unit loads.   C[m,n] = sum_k A[m,k] * Wt[n,k]
// CTA 128x128, 8 warps (2m x 4n), warp 64x32, K-chunk 32, single-stage smem.
// EPI 0: plain fp32      EPI 1: transposed (b,c,l) final output
// EPI 3: softplus(v+eb[n])      EPI 4: BN+ReLU6
// ----------------------------------------------------------------------------
#define SOFF_AH 0
#define SOFF_AL 8192
#define SOFF_BH 16384
#define SOFF_BL 24576

template <int EPI>
__global__ __launch_bounds__(256)
void mma_gemm_kernel(const float* __restrict__ A, int lda,
                     const float* __restrict__ Wt, int ldw,
                     float* __restrict__ C, int ldc,
                     int M, int N, int K,
                     const float* __restrict__ ea, const float* __restrict__ eb) {
    __shared__ __align__(16) unsigned char smem_buf[34048];
    const uint32_t sbase = smem_to_u32(smem_buf);
    const int tid = threadIdx.x;
    const int lane = tid & 31, wid = tid >> 5;
    const int wm = wid >> 2, wn = wid & 3;
    const int bm = blockIdx.y * 128, bn = blockIdx.x * 128;
    const int nchunks = (K + 31) / 32;
    const bool alA = ((lda & 1) == 0);
    const bool alB = ((ldw & 1) == 0);

    float acc[4][4][4];
    #pragma unroll
    for (int i = 0; i < 4; i++)
        #pragma unroll
        for (int j = 0; j < 4; j++)
            #pragma unroll
            for (int q = 0; q < 4; q++) acc[i][j][q] = 0.f;

    const int lrow = lane & 15;     // ldmatrix row within 16-row tile
    const int lkh  = lane >> 4;     // k-half select

    // per-thread load coordinates (2 units of 8 fp32 per matrix)
    int lrr[2], lcc[2];
    uint32_t lsw[2];
    bool lar[2], lbr[2];
    #pragma unroll
    for (int uu = 0; uu < 2; uu++) {
        int u = tid + uu * 256;
        lrr[uu] = u >> 2; lcc[uu] = u & 3;
        lsw[uu] = (uint32_t)(lrr[uu] * 64 + ((lcc[uu] ^ ((lrr[uu] >> 1) & 3)) << 4));
        lar[uu] = (bm + lrr[uu]) < M;
        lbr[uu] = (bn + lrr[uu]) < N;
    }

    float pa[2][8], pb[2][8];

    // ---- prologue: load chunk 0 ----
    #pragma unroll
    for (int uu = 0; uu < 2; uu++) {
        int gk = lcc[uu] * 8;
        load_unit(A  + (size_t)(bm + lrr[uu]) * lda + gk, lar[uu], K - gk, alA, pa[uu]);
        load_unit(Wt + (size_t)(bn + lrr[uu]) * ldw + gk, lbr[uu], K - gk, alB, pb[uu]);
    }

    for (int ch = 0; ch < nchunks; ch++) {
        // ---- convert + store current chunk regs into smem ----
        #pragma unroll
        for (int uu = 0; uu < 2; uu++) {
            uint4 hi, lo;
            cvt_hilo(pa[uu], hi, lo);
            *(uint4*)(smem_buf + SOFF_AH + lsw[uu]) = hi;
            *(uint4*)(smem_buf + SOFF_AL + lsw[uu]) = lo;
            cvt_hilo(pb[uu], hi, lo);
            *(uint4*)(smem_buf + SOFF_BH + lsw[uu]) = hi;
            *(uint4*)(smem_buf + SOFF_BL + lsw[uu]) = lo;
        }
        __syncthreads();

        // ---- issue next chunk's global loads (overlaps the MMA below) ----
        if (ch + 1 < nchunks) {
            int k0n = (ch + 1) * 32;
            #pragma unroll
            for (int uu = 0; uu < 2; uu++) {
                int gk = k0n + lcc[uu] * 8;
                load_unit(A  + (size_t)(bm + lrr[uu]) * lda + gk, lar[uu], K - gk, alA, pa[uu]);
                load_unit(Wt + (size_t)(bn + lrr[uu]) * ldw + gk, lbr[uu], K - gk, alB, pb[uu]);
            }
        }

        // ---- MMA over the staged 32-K chunk (two k16 steps) ----
        #pragma unroll
        for (int k16 = 0; k16 < 2; k16++) {
            const int cbase = k16 * 2 + lkh;
            uint32_t ahf[4][4], alf[4][4], bhf[4][2], blf[4][2];
            #pragma unroll
            for (int mi = 0; mi < 4; mi++) {
                int r = wm * 64 + mi * 16 + lrow;
                uint32_t off = (uint32_t)(r * 64 + ((cbase ^ ((r >> 1) & 3)) << 4));
                ldsm4(ahf[mi], sbase + SOFF_AH + off);
                ldsm4(alf[mi], sbase + SOFF_AL + off);
            }
            #pragma unroll
            for (int ni = 0; ni < 2; ni++) {
                int r = wn * 32 + ni * 16 + lrow;
                uint32_t off = (uint32_t)(r * 64 + ((cbase ^ ((r >> 1) & 3)) << 4));
                uint32_t bt[4];
                ldsm4(bt, sbase + SOFF_BH + off);
                bhf[ni * 2 + 0][0] = bt[0]; bhf[ni * 2 + 0][1] = bt[2];
                bhf[ni * 2 + 1][0] = bt[1]; bhf[ni * 2 + 1][1] = bt[3];
                ldsm4(bt, sbase + SOFF_BL + off);
                blf[ni * 2 + 0][0] = bt[0]; blf[ni * 2 + 0][1] = bt[2];
                blf[ni * 2 + 1][0] = bt[1]; blf[ni * 2 + 1][1] = bt[3];
            }
            #pragma unroll
            for (int mi = 0; mi < 4; mi++)
                #pragma unroll
                for (int nj = 0; nj < 4; nj++) {
                    mma16816(acc[mi][nj], ahf[mi], bhf[nj][0], bhf[nj][1]);
                    mma16816(acc[mi][nj], ahf[mi], blf[nj][0], blf[nj][1]);
                    mma16816(acc[mi][nj], alf[mi], bhf[nj][0], bhf[nj][1]);
                }
        }
        __syncthreads();
    }

    // ---- epilogue: two passes (warps wm==0 then wm==1) reusing tile smem ----
    const int m0 = bm + wm * 64, n0 = bn + wn * 32;
    const int tr = lane >> 2, tc2 = (lane & 3) * 2;
    #pragma unroll
    for (int pass = 0; pass < 2; pass++) {
        __syncthreads();
        if (wm == pass) {
            float* tp = (float*)(smem_buf + (size_t)wn * 8448);   // 64x33 floats
            #pragma unroll
            for (int mi = 0; mi < 4; mi++)
                #pragma unroll
                for (int nj = 0; nj < 4; nj++) {
                    int r0 = mi * 16 + tr, c0 = nj * 8 + tc2;
                    tp[r0 * 33 + c0]           = acc[mi][nj][0];
                    tp[r0 * 33 + c0 + 1]       = acc[mi][nj][1];
                    tp[(r0 + 8) * 33 + c0]     = acc[mi][nj][2];
                    tp[(r0 + 8) * 33 + c0 + 1] = acc[mi][nj][3];
                }
            __syncwarp();
            if (EPI == 0) {
                int gn = n0 + lane;
                if (gn < N)
                    for (int r = 0; r < 64; r++) {
                        int gm = m0 + r;
                        if (gm < M) C[(size_t)gm * ldc + gn] = tp[r * 33 + lane];
                    }
            } else if (EPI == 3) {
                int gn = n0 + lane;
                if (gn < N) {
                    float bias = eb[gn];
                    for (int r = 0; r < 64; r++) {
                        int gm = m0 + r;
                        if (gm >= M) break;
                        float v = tp[r * 33 + lane] + bias;
                        v = (v > 20.f) ? v : log1pf(expf(v));
                        C[(size_t)gm * ldc + gn] = v;
                    }
                }
            } else if (EPI == 4) {
                int gn = n0 + lane;
                if (gn < N) {
                    float sa = ea[gn], sb = eb[gn];
                    for (int r = 0; r < 64; r++) {
                        int gm = m0 + r;
                        if (gm >= M) break;
                        float v = tp[r * 33 + lane] * sa + sb;
                        v = fminf(fmaxf(v, 0.f), 6.f);
                        C[(size_t)gm * ldc + gn] = v;
                    }
                }
            } else {  // EPI 1: transposed final output (b, c, l); M == 16384
                for (int c = 0; c < 32; c++) {
                    int gn = n0 + c;
                    if (gn >= N) break;
                    int m = m0 + lane;
                    int b = m >> 8, l = m & 255;
                    C[((size_t)(b * D_MODEL + gn)) * L_SEQ + l] = tp[lane * 33 + c];
                    m = m0 + 32 + lane;
                    b = m >> 8; l = m & 255;
                    C[((size_t)(b * D_MODEL + gn)) * L_SEQ + l] = tp[(lane + 32) * 33 + c];
                }
            }
        }
    }
}

// ----------------------------------------------------------------------------
__global__ void prep_bn_kernel(const float* __restrict__ gamma,
                               const float* __restrict__ beta,
                               const float* __restrict__ mean,
                               const float* __restrict__ var) {
    int i = blockIdx.x * 256 + threadIdx.x;
    if (i < 4 * DIM) {
        float iv = rsqrtf(var[i] + 1e-5f) * gamma[i];
        g_bninv[i]  = iv;
        g_bnbias[i] = beta[i] - mean[i] * iv;
    }
}

// ----------------------------------------------------------------------------
__global__ void build_comb_kernel(const float* __restrict__ x,
                                  const float* __restrict__ pc) {
    size_t idx = (size_t)blockIdx.x * 256 + threadIdx.x;
    if (idx >= (size_t)BATCH * COMB * L_SEQ) return;
    int l = (int)(idx % L_SEQ);
    int c = (int)((idx / L_SEQ) % COMB);
    int b = (int)(idx / ((size_t)L_SEQ * COMB));
    float v;
    if (c < IN_IMG) {
        v = x[((size_t)(b * IN_IMG + c)) * L_SEQ + l];
    } else if (c == IN_IMG) {
        int w = l & 15;
        v = -0.3f + 0.6f * (float)w / 15.0f;
    } else if (c == IN_IMG + 1) {
        int h = l >> 4;
        v = -0.3f + 0.6f * (float)h / 15.0f;
    } else {
        v = pc[b * IN_PC + (c - IN_IMG - 2)];
    }
    g_comb[((size_t)(b * COMB + c)) * L_SEQ + l] = v;
    g_seq[((size_t)(b * L_SEQ + l)) * D_MODEL + c] = v;
}

// ----------------------------------------------------------------------------
__global__ void pool_avg_kernel() {
    __shared__ float s[32][257];
    int b  = blockIdx.y;
    int c0 = blockIdx.x * 32;
    int tid = threadIdx.x;
    for (int i = tid; i < 32 * 256; i += 256) {
        int cl = i >> 8, l = i & 255;
        int c = c0 + cl;
        s[cl][l] = (c < COMB) ? g_comb[((size_t)(b * COMB + c)) * L_SEQ + l] : 0.f;
    }
    __syncthreads();
    for (int oidx = tid; oidx < 275 * 32; oidx += 256) {
        int cl = oidx & 31;
        int q  = oidx >> 5;
        int sdim, qb, base;
        if (q < 25)       { sdim = 5;  qb = q;       base = POOL5_OFF;  }
        else if (q < 106) { sdim = 9;  qb = q - 25;  base = POOL9_OFF;  }
        else              { sdim = 13; qb = q - 106; base = POOL13_OFF; }
        int o = qb / sdim, p = qb % sdim;
        int h0 = (o * 16) / sdim, h1 = ((o + 1) * 16 + sdim - 1) / sdim;
        int w0 = (p * 16) / sdim, w1 = ((p + 1) * 16 + sdim - 1) / sdim;
        float sum = 0.f;
        for (int h = h0; h < h1; h++)
            for (int w = w0; w < w1; w++)
                sum += s[cl][h * 16 + w];
        sum *= 1.0f / (float)((h1 - h0) * (w1 - w0));
        int c = c0 + cl;
        if (c < COMB)
            g_pooled[((size_t)(base + b * sdim * sdim + qb)) * COMB + c] = sum;
    }
}

// ----------------------------------------------------------------------------
__global__ void pool0_mean_kernel() {
    int b = blockIdx.x;
    int d = threadIdx.x;
    float s = 0.f;
    for (int l = 0; l < L_SEQ; l++)
        s += g_p0[((size_t)(b * L_SEQ + l)) * DIM + d];
    g_y0[b * DIM + d] = s * (1.0f / (float)L_SEQ);
}

// ----------------------------------------------------------------------------
__global__ void fill_pool_cols_kernel() {
    int m = blockIdx.x;
    int t = threadIdx.x;
    int b = m >> 8, l = m & 255;
    int h = l >> 4, w = l & 15;
    int si = t >> 7, d = t & 127;
    float v;
    if (si == 0) {
        v = g_y0[b * DIM + d];
    } else {
        int sdim = (si == 1) ? 5 : (si == 2) ? 9 : 13;
        int base = (si == 1) ? POOL5_OFF : (si == 2) ? POOL9_OFF : POOL13_OFF;
        float sh = (h + 0.5f) * (float)sdim / 16.0f - 0.5f;
        sh = fminf(fmaxf(sh, 0.f), (float)sdim - 1.f);
        int h0 = (int)sh;
        int h1 = min(h0 + 1, sdim - 1);
        float fh = sh - (float)h0;
        float sw = (w + 0.5f) * (float)sdim / 16.0f - 0.5f;
        sw = fminf(fmaxf(sw, 0.f), (float)sdim - 1.f);
        int w0 = (int)sw;
        int w1 = min(w0 + 1, sdim - 1);
        float fw = sw - (float)w0;
        const float* Y = g_ys + (size_t)(base + b * sdim * sdim) * DIM;
        float v00 = Y[(size_t)(h0 * sdim + w0) * DIM + d];
        float v01 = Y[(size_t)(h0 * sdim + w1) * DIM + d];
        float v10 = Y[(size_t)(h1 * sdim + w0) * DIM + d];
        float v11 = Y[(size_t)(h1 * sdim + w1) * DIM + d];
        v = (1.f - fh) * ((1.f - fw) * v00 + fw * v01)
          +        fh  * ((1.f - fw) * v10 + fw * v11);
    }
    g_seq[(size_t)m * D_MODEL + COMB + t] = v;
}

// ----------------------------------------------------------------------------
__global__ void conv1d_silu_kernel(const float* __restrict__ w,
                                   const float* __restrict__ bias) {
    int d = blockIdx.x * 256 + threadIdx.x;
    int m = blockIdx.y;
    if (d >= D_INNER) return;
    int b = m >> 8, l = m & 255;
    float acc = bias[d];
    #pragma unroll
    for (int k = 0; k < D_CONV; k++) {
        int ls = l + k - (D_CONV - 1);
        if (ls >= 0)
            acc += w[d * D_CONV + k] * g_xz[((size_t)(b * L_SEQ + ls)) * (2 * D_INNER) + d];
    }
    float sg = 1.f / (1.f + __expf(-acc));
    g_uact[(size_t)m * D_INNER + d] = acc * sg;
}

// ----------------------------------------------------------------------------
__global__ __launch_bounds__(256)
void scan_kernel(const float* __restrict__ A_log, const float* __restrict__ Dp) {
    __shared__ float sB[L_SEQ][D_STATE];
    __shared__ float sC[L_SEQ][D_STATE];
    int b = blockIdx.y;
    int d = blockIdx.x * 256 + threadIdx.x;
    int tid = threadIdx.x;
    for (int i = tid; i < L_SEQ * D_STATE; i += 256) {
        int l = i >> 4, n = i & 15;
        const float* row = g_dbl + (size_t)(b * L_SEQ + l) * XPROJ_LD;
        sB[l][n] = row[DT_RANK + n];
        sC[l][n] = row[DT_RANK + D_STATE + n];
    }
    __syncthreads();
    if (d >= D_INNER) return;

    float Ad[D_STATE];
    #pragma unroll
    for (int n = 0; n < D_STATE; n++) Ad[n] = -expf(A_log[d * D_STATE + n]);
    float Dd = Dp[d];
    float h[D_STATE];
    #pragma unroll
    for (int n = 0; n < D_STATE; n++) h[n] = 0.f;

    for (int l = 0; l < L_SEQ; l++) {
        size_t m = (size_t)(b * L_SEQ + l);
        float dt = g_dt[m * D_INNER + d];
        float u  = g_uact[m * D_INNER + d];
        float z  = g_xz[m * (2 * D_INNER) + D_INNER + d];
        float dtu = dt * u;
        float y = 0.f;
        #pragma unroll
        for (int n = 0; n < D_STATE; n++) {
            float dA = __expf(dt * Ad[n]);
            h[n] = dA * h[n] + dtu * sB[l][n];
            y = fmaf(h[n], sC[l][n], y);
        }
        float sig = 1.f / (1.f + __expf(-z));
        g_y[m * D_INNER + d] = (y + u * Dd) * (z * sig);
    }
}

// ----------------------------------------------------------------------------
extern "C" void kernel_launch(void* const* d_in, const int* in_sizes, int n_in,
                              void* d_out, int out_size) {
    const float* x          = (const float*)d_in[0];
    const float* pc_emb     = (const float*)d_in[1];
    const float* conv_w     = (const float*)d_in[2];
    const float* bn_gamma   = (const float*)d_in[3];
    const float* bn_beta    = (const float*)d_in[4];
    const float* bn_mean    = (const float*)d_in[5];
    const float* bn_var     = (const float*)d_in[6];
    const float* in_proj_w  = (const float*)d_in[7];
    const float* conv1d_w   = (const float*)d_in[8];
    const float* conv1d_b   = (const float*)d_in[9];
    const float* x_proj_w   = (const float*)d_in[10];
    const float* dt_proj_w  = (const float*)d_in[11];
    const float* dt_proj_b  = (const float*)d_in[12];
    const float* A_log      = (const float*)d_in[13];
    const float* Dp         = (const float*)d_in[14];
    const float* out_proj_w = (const float*)d_in[15];
    float* out = (float*)d_out;

    float *p_seq, *p_xz, *p_uact, *p_dbl, *p_dt, *p_y, *p_p0, *p_pooled, *p_ys;
    float *p_bninv, *p_bnbias;
    cudaGetSymbolAddress((void**)&p_seq,    g_seq);
    cudaGetSymbolAddress((void**)&p_xz,     g_xz);
    cudaGetSymbolAddress((void**)&p_uact,   g_uact);
    cudaGetSymbolAddress((void**)&p_dbl,    g_dbl);
    cudaGetSymbolAddress((void**)&p_dt,     g_dt);
    cudaGetSymbolAddress((void**)&p_y,      g_y);
    cudaGetSymbolAddress((void**)&p_p0,     g_p0);
    cudaGetSymbolAddress((void**)&p_pooled, g_pooled);
    cudaGetSymbolAddress((void**)&p_ys,     g_ys);
    cudaGetSymbolAddress((void**)&p_bninv,  g_bninv);
    cudaGetSymbolAddress((void**)&p_bnbias, g_bnbias);

    // 1) BN fold
    prep_bn_kernel<<<2, 256>>>(bn_gamma, bn_beta, bn_mean, bn_var);

    // 2) build comb (both layouts)
    {
        size_t total = (size_t)BATCH * COMB * L_SEQ;
        build_comb_kernel<<<(unsigned)((total + 255) / 256), 256>>>(x, pc_emb);
    }

    // 3) adaptive pools for scales 5/9/13
    pool_avg_kernel<<<dim3(25, BATCH), 256>>>();

    // 4) conv0 full-res (HMMA, BN+ReLU6)
    mma_gemm_kernel<4><<<dim3(1, M_TOTAL / 128), 256>>>(
        p_seq, D_MODEL, conv_w, COMB, p_p0, DIM,
        M_TOTAL, DIM, COMB, p_bninv, p_bnbias);

    // 5) pool0 mean
    pool0_mean_kernel<<<BATCH, DIM>>>();

    // 6) pooled-branch convs (HMMA, BN+ReLU6)
    {
        const int sM[3]   = {1600, 5184, 10816};
        const int sOff[3] = {POOL5_OFF, POOL9_OFF, POOL13_OFF};
        for (int i = 0; i < 3; i++) {
            int pool = i + 1;
            mma_gemm_kernel<4><<<dim3(1, (sM[i] + 127) / 128), 256>>>(
                p_pooled + (size_t)sOff[i] * COMB, COMB,
                conv_w + (size_t)pool * DIM * COMB, COMB,
                p_ys + (size_t)sOff[i] * DIM, DIM,
                sM[i], DIM, COMB,
                p_bninv + pool * DIM, p_bnbias + pool * DIM);
        }
    }

    // 7) fill pool columns of seq
    fill_pool_cols_kernel<<<M_TOTAL, 512>>>();

    // 8) in_proj (HMMA) -> g_xz
    mma_gemm_kernel<0><<<dim3((2 * D_INNER + 127) / 128, M_TOTAL / 128), 256>>>(
        p_seq, D_MODEL, in_proj_w, D_MODEL, p_xz, 2 * D_INNER,
        M_TOTAL, 2 * D_INNER, D_MODEL, nullptr, nullptr);

    // 9) depthwise causal conv1d + SiLU
    conv1d_silu_kernel<<<dim3((D_INNER + 255) / 256, M_TOTAL), 256>>>(conv1d_w, conv1d_b);

    // 10) x_proj (HMMA) -> g_dbl (padded ldc)
    mma_gemm_kernel<0><<<dim3(1, M_TOTAL / 128), 256>>>(
        p_uact, D_INNER, x_proj_w, D_INNER, p_dbl, XPROJ_LD,
        M_TOTAL, XPROJ_N, D_INNER, nullptr, nullptr);

    // 11) dt_proj (HMMA, softplus) -> g_dt   (A = first 81 cols of g_dbl)
    mma_gemm_kernel<3><<<dim3((D_INNER + 127) / 128, M_TOTAL / 128), 256>>>(
        p_dbl, XPROJ_LD, dt_proj_w, DT_RANK, p_dt, D_INNER,
        M_TOTAL, D_INNER, DT_RANK, nullptr, dt_proj_b);

    // 12) selective scan (fused output gate)
    scan_kernel<<<dim3((D_INNER + 255) / 256, BATCH), 256>>>(A_log, Dp);

    // 13) out_proj (HMMA, fused transpose) -> out
    mma_gemm_kernel<1><<<dim3((D_MODEL + 127) / 128, M_TOTAL / 128), 256>>>(
        p_y, D_INNER, out_proj_w, D_INNER, out, 0,
        M_TOTAL, D_MODEL, D_INNER, nullptr, nullptr);
}

// round 10
// speedup vs baseline: 1.1432x; 1.1432x over previous
#include <cuda_runtime.h>
#include <cuda_bf16.h>
#include <cstdint>

// ----------------------------------------------------------------------------
// Problem constants
// ----------------------------------------------------------------------------
#define BATCH     64
#define L_SEQ     256
#define IN_IMG    512
#define IN_PC     256
#define COMB      770
#define DIM       128
#define D_MODEL   1282
#define D_INNER   2564
#define D_STATE   16
#define D_CONV    4
#define DT_RANK   81
#define XPROJ_N   113
#define XPROJ_LD  116            // padded leading dim of g_dbl (even, 8B rows)
#define M_TOTAL   (BATCH * L_SEQ)      // 16384

#define POOL5_OFF   0
#define POOL9_OFF   1600
#define POOL13_OFF  6784
#define POOL_ROWS   17600

// ----------------------------------------------------------------------------
// Device scratch (static — proven set; g_dbl padded to XPROJ_LD)
// ----------------------------------------------------------------------------
__device__ __align__(16) float g_seq   [(size_t)M_TOTAL * D_MODEL];
__device__ __align__(16) float g_comb  [(size_t)BATCH * COMB * L_SEQ];
__device__ __align__(16) float g_xz    [(size_t)M_TOTAL * 2 * D_INNER];
__device__ __align__(16) float g_uact  [(size_t)M_TOTAL * D_INNER];
__device__ __align__(16) float g_dbl   [(size_t)M_TOTAL * XPROJ_LD];
__device__ __align__(16) float g_dt    [(size_t)M_TOTAL * D_INNER];
__device__ __align__(16) float g_y     [(size_t)M_TOTAL * D_INNER];
__device__ __align__(16) float g_p0    [(size_t)M_TOTAL * DIM];
__device__ __align__(16) float g_y0    [BATCH * DIM];
__device__ __align__(16) float g_pooled[(size_t)POOL_ROWS * COMB];
__device__ __align__(16) float g_ys    [(size_t)POOL_ROWS * DIM];
__device__ __align__(16) float g_bninv [4 * DIM];
__device__ __align__(16) float g_bnbias[4 * DIM];

// ----------------------------------------------------------------------------
// PTX helpers (baseline-ISA only: ldmatrix + mma.sync)
// ----------------------------------------------------------------------------
__device__ __forceinline__ uint32_t smem_to_u32(const void* p) {
    uint32_t a;
    asm("{ .reg .u64 t; cvta.to.shared.u64 t, %1; cvt.u32.u64 %0, t; }"
        : "=r"(a) : "l"(p));
    return a;
}
__device__ __forceinline__ void ldsm4(uint32_t* f, uint32_t addr) {
    asm volatile("ldmatrix.sync.aligned.m8n8.x4.shared.b16 {%0,%1,%2,%3}, [%4];"
                 : "=r"(f[0]), "=r"(f[1]), "=r"(f[2]), "=r"(f[3]) : "r"(addr));
}
__device__ __forceinline__ void mma16816(float* d, const uint32_t* a,
                                         uint32_t b0, uint32_t b1) {
    asm volatile(
        "mma.sync.aligned.m16n8k16.row.col.f32.bf16.bf16.f32 "
        "{%0,%1,%2,%3}, {%4,%5,%6,%7}, {%8,%9}, {%0,%1,%2,%3};"
        : "+f"(d[0]), "+f"(d[1]), "+f"(d[2]), "+f"(d[3])
        : "r"(a[0]), "r"(a[1]), "r"(a[2]), "r"(a[3]), "r"(b0), "r"(b1));
}

// fp32[8] -> bf16 hi uint4 + bf16 lo uint4
__device__ __forceinline__ void cvt_hilo(const float* v, uint4& hi, uint4& lo) {
    uint32_t h[4], l[4];
    #pragma unroll
    for (int i = 0; i < 4; i++) {
        __nv_bfloat16 h0 = __float2bfloat16(v[2*i]);
        __nv_bfloat16 h1 = __float2bfloat16(v[2*i+1]);
        float r0 = v[2*i]   - __bfloat162float(h0);
        float r1 = v[2*i+1] - __bfloat162float(h1);
        __nv_bfloat16 l0 = __float2bfloat16(r0);
        __nv_bfloat16 l1 = __float2bfloat16(r1);
        h[i] = (uint32_t)__bfloat16_as_ushort(h0) | ((uint32_t)__bfloat16_as_ushort(h1) << 16);
        l[i] = (uint32_t)__bfloat16_as_ushort(l0) | ((uint32_t)__bfloat16_as_ushort(l1) << 16);
    }
    hi = make_uint4(h[0], h[1], h[2], h[3]);
    lo = make_uint4(l[0], l[1], l[2], l[3]);
}

// 8-float unit load: vectorized float2 x4 fast path when the unit is fully
// in-bounds and rows are 8B-aligned (even lda); guarded scalar path otherwise.
__device__ __forceinline__ void load_unit(const float* p, bool rowok, int krem,
                                          bool al8, float* v) {
    if (rowok && al8 && krem >= 8) {
        const float2* q = (const float2*)p;
        float2 a = q[0], b = q[1], c = q[2], d = q[3];
        v[0] = a.x; v[1] = a.y; v[2] = b.x; v[3] = b.y;
        v[4] = c.x; v[5] = c.y; v[6] = d.x; v[7] = d.y;
    } else {
        #pragma unroll
        for (int i = 0; i < 8; i++)
            v[i] = (rowok && i < krem) ? p[i] : 0.f;
    }
}

// ----------------------------------------------------------------------------
// HMMA bf16x3-split GEMM, in-register split, vectorized unit loads,
// NO register prefetch (prefetch builds measured slower in total).
//   C[m,n] = sum_k A[m,k] * Wt[n,k]
// CTA 128x128, 8 warps (2m x 4n), warp 64x32, K-chunk 32, single-stage smem.
// EPI 0: plain fp32      EPI 1: transposed (b,c,l) final output
// EPI 3: softplus(v+eb[n])      EPI 4: BN+ReLU6
// ----------------------------------------------------------------------------
#define SOFF_AH 0
#define SOFF_AL 8192
#define SOFF_BH 16384
#define SOFF_BL 24576

template <int EPI>
__global__ __launch_bounds__(256)
void mma_gemm_kernel(const float* __restrict__ A, int lda,
                     const float* __restrict__ Wt, int ldw,
                     float* __restrict__ C, int ldc,
                     int M, int N, int K,
                     const float* __restrict__ ea, const float* __restrict__ eb) {
    __shared__ __align__(16) unsigned char smem_buf[34048];
    const uint32_t sbase = smem_to_u32(smem_buf);
    const int tid = threadIdx.x;
    const int lane = tid & 31, wid = tid >> 5;
    const int wm = wid >> 2, wn = wid & 3;
    const int bm = blockIdx.y * 128, bn = blockIdx.x * 128;
    const int nchunks = (K + 31) / 32;
    const bool alA = ((lda & 1) == 0);
    const bool alB = ((ldw & 1) == 0);

    float acc[4][4][4];
    #pragma unroll
    for (int i = 0; i < 4; i++)
        #pragma unroll
        for (int j = 0; j < 4; j++)
            #pragma unroll
            for (int q = 0; q < 4; q++) acc[i][j][q] = 0.f;

    const int lrow = lane & 15;     // ldmatrix row within 16-row tile
    const int lkh  = lane >> 4;     // k-half select

    for (int ch = 0; ch < nchunks; ch++) {
        const int k0 = ch * 32;
        // ---- load + split + store: 512 16B units per matrix, 2 per thread ----
        #pragma unroll
        for (int uu = 0; uu < 2; uu++) {
            int u = tid + uu * 256;
            int r = u >> 2, cu = u & 3;
            uint32_t soff = (uint32_t)(r * 64 + ((cu ^ ((r >> 1) & 3)) << 4));
            int gk = k0 + cu * 8;
            float va[8];
            load_unit(A + (size_t)(bm + r) * lda + gk, (bm + r) < M, K - gk, alA, va);
            uint4 hi, lo;
            cvt_hilo(va, hi, lo);
            *(uint4*)(smem_buf + SOFF_AH + soff) = hi;
            *(uint4*)(smem_buf + SOFF_AL + soff) = lo;
            load_unit(Wt + (size_t)(bn + r) * ldw + gk, (bn + r) < N, K - gk, alB, va);
            cvt_hilo(va, hi, lo);
            *(uint4*)(smem_buf + SOFF_BH + soff) = hi;
            *(uint4*)(smem_buf + SOFF_BL + soff) = lo;
        }
        __syncthreads();
        // ---- mma over the 32-K chunk (two k16 steps) ----
        #pragma unroll
        for (int k16 = 0; k16 < 2; k16++) {
            const int cbase = k16 * 2 + lkh;
            uint32_t ahf[4][4], alf[4][4], bhf[4][2], blf[4][2];
            #pragma unroll
            for (int mi = 0; mi < 4; mi++) {
                int r = wm * 64 + mi * 16 + lrow;
                uint32_t off = (uint32_t)(r * 64 + ((cbase ^ ((r >> 1) & 3)) << 4));
                ldsm4(ahf[mi], sbase + SOFF_AH + off);
                ldsm4(alf[mi], sbase + SOFF_AL + off);
            }
            #pragma unroll
            for (int ni = 0; ni < 2; ni++) {
                int r = wn * 32 + ni * 16 + lrow;
                uint32_t off = (uint32_t)(r * 64 + ((cbase ^ ((r >> 1) & 3)) << 4));
                uint32_t bt[4];
                ldsm4(bt, sbase + SOFF_BH + off);
                bhf[ni * 2 + 0][0] = bt[0]; bhf[ni * 2 + 0][1] = bt[2];
                bhf[ni * 2 + 1][0] = bt[1]; bhf[ni * 2 + 1][1] = bt[3];
                ldsm4(bt, sbase + SOFF_BL + off);
                blf[ni * 2 + 0][0] = bt[0]; blf[ni * 2 + 0][1] = bt[2];
                blf[ni * 2 + 1][0] = bt[1]; blf[ni * 2 + 1][1] = bt[3];
            }
            #pragma unroll
            for (int mi = 0; mi < 4; mi++)
                #pragma unroll
                for (int nj = 0; nj < 4; nj++) {
                    mma16816(acc[mi][nj], ahf[mi], bhf[nj][0], bhf[nj][1]);
                    mma16816(acc[mi][nj], ahf[mi], blf[nj][0], blf[nj][1]);
                    mma16816(acc[mi][nj], alf[mi], bhf[nj][0], bhf[nj][1]);
                }
        }
        __syncthreads();
    }

    // ---- epilogue: two passes (warps wm==0 then wm==1) reusing tile smem ----
    const int m0 = bm + wm * 64, n0 = bn + wn * 32;
    const int tr = lane >> 2, tc2 = (lane & 3) * 2;
    #pragma unroll
    for (int pass = 0; pass < 2; pass++) {
        __syncthreads();
        if (wm == pass) {
            float* tp = (float*)(smem_buf + (size_t)wn * 8448);   // 64x33 floats
            #pragma unroll
            for (int mi = 0; mi < 4; mi++)
                #pragma unroll
                for (int nj = 0; nj < 4; nj++) {
                    int r0 = mi * 16 + tr, c0 = nj * 8 + tc2;
                    tp[r0 * 33 + c0]           = acc[mi][nj][0];
                    tp[r0 * 33 + c0 + 1]       = acc[mi][nj][1];
                    tp[(r0 + 8) * 33 + c0]     = acc[mi][nj][2];
                    tp[(r0 + 8) * 33 + c0 + 1] = acc[mi][nj][3];
                }
            __syncwarp();
            if (EPI == 0) {
                int gn = n0 + lane;
                if (gn < N)
                    for (int r = 0; r < 64; r++) {
                        int gm = m0 + r;
                        if (gm < M) C[(size_t)gm * ldc + gn] = tp[r * 33 + lane];
                    }
            } else if (EPI == 3) {
                int gn = n0 + lane;
                if (gn < N) {
                    float bias = eb[gn];
                    for (int r = 0; r < 64; r++) {
                        int gm = m0 + r;
                        if (gm >= M) break;
                        float v = tp[r * 33 + lane] + bias;
                        v = (v > 20.f) ? v : log1pf(expf(v));
                        C[(size_t)gm * ldc + gn] = v;
                    }
                }
            } else if (EPI == 4) {
                int gn = n0 + lane;
                if (gn < N) {
                    float sa = ea[gn], sb = eb[gn];
                    for (int r = 0; r < 64; r++) {
                        int gm = m0 + r;
                        if (gm >= M) break;
                        float v = tp[r * 33 + lane] * sa + sb;
                        v = fminf(fmaxf(v, 0.f), 6.f);
                        C[(size_t)gm * ldc + gn] = v;
                    }
                }
            } else {  // EPI 1: transposed final output (b, c, l); M == 16384
                for (int c = 0; c < 32; c++) {
                    int gn = n0 + c;
                    if (gn >= N) break;
                    int m = m0 + lane;
                    int b = m >> 8, l = m & 255;
                    C[((size_t)(b * D_MODEL + gn)) * L_SEQ + l] = tp[lane * 33 + c];
                    m = m0 + 32 + lane;
                    b = m >> 8; l = m & 255;
                    C[((size_t)(b * D_MODEL + gn)) * L_SEQ + l] = tp[(lane + 32) * 33 + c];
                }
            }
        }
    }
}

// ----------------------------------------------------------------------------
__global__ void prep_bn_kernel(const float* __restrict__ gamma,
                               const float* __restrict__ beta,
                               const float* __restrict__ mean,
                               const float* __restrict__ var) {
    int i = blockIdx.x * 256 + threadIdx.x;
    if (i < 4 * DIM) {
        float iv = rsqrtf(var[i] + 1e-5f) * gamma[i];
        g_bninv[i]  = iv;
        g_bnbias[i] = beta[i] - mean[i] * iv;
    }
}

// ----------------------------------------------------------------------------
__global__ void build_comb_kernel(const float* __restrict__ x,
                                  const float* __restrict__ pc) {
    size_t idx = (size_t)blockIdx.x * 256 + threadIdx.x;
    if (idx >= (size_t)BATCH * COMB * L_SEQ) return;
    int l = (int)(idx % L_SEQ);
    int c = (int)((idx / L_SEQ) % COMB);
    int b = (int)(idx / ((size_t)L_SEQ * COMB));
    float v;
    if (c < IN_IMG) {
        v = x[((size_t)(b * IN_IMG + c)) * L_SEQ + l];
    } else if (c == IN_IMG) {
        int w = l & 15;
        v = -0.3f + 0.6f * (float)w / 15.0f;
    } else if (c == IN_IMG + 1) {
        int h = l >> 4;
        v = -0.3f + 0.6f * (float)h / 15.0f;
    } else {
        v = pc[b * IN_PC + (c - IN_IMG - 2)];
    }
    g_comb[((size_t)(b * COMB + c)) * L_SEQ + l] = v;
    g_seq[((size_t)(b * L_SEQ + l)) * D_MODEL + c] = v;
}

// ----------------------------------------------------------------------------
__global__ void pool_avg_kernel() {
    __shared__ float s[32][257];
    int b  = blockIdx.y;
    int c0 = blockIdx.x * 32;
    int tid = threadIdx.x;
    for (int i = tid; i < 32 * 256; i += 256) {
        int cl = i >> 8, l = i & 255;
        int c = c0 + cl;
        s[cl][l] = (c < COMB) ? g_comb[((size_t)(b * COMB + c)) * L_SEQ + l] : 0.f;
    }
    __syncthreads();
    for (int oidx = tid; oidx < 275 * 32; oidx += 256) {
        int cl = oidx & 31;
        int q  = oidx >> 5;
        int sdim, qb, base;
        if (q < 25)       { sdim = 5;  qb = q;       base = POOL5_OFF;  }
        else if (q < 106) { sdim = 9;  qb = q - 25;  base = POOL9_OFF;  }
        else              { sdim = 13; qb = q - 106; base = POOL13_OFF; }
        int o = qb / sdim, p = qb % sdim;
        int h0 = (o * 16) / sdim, h1 = ((o + 1) * 16 + sdim - 1) / sdim;
        int w0 = (p * 16) / sdim, w1 = ((p + 1) * 16 + sdim - 1) / sdim;
        float sum = 0.f;
        for (int h = h0; h < h1; h++)
            for (int w = w0; w < w1; w++)
                sum += s[cl][h * 16 + w];
        sum *= 1.0f / (float)((h1 - h0) * (w1 - w0));
        int c = c0 + cl;
        if (c < COMB)
            g_pooled[((size_t)(base + b * sdim * sdim + qb)) * COMB + c] = sum;
    }
}

// ----------------------------------------------------------------------------
__global__ void pool0_mean_kernel() {
    int b = blockIdx.x;
    int d = threadIdx.x;
    float s = 0.f;
    for (int l = 0; l < L_SEQ; l++)
        s += g_p0[((size_t)(b * L_SEQ + l)) * DIM + d];
    g_y0[b * DIM + d] = s * (1.0f / (float)L_SEQ);
}

// ----------------------------------------------------------------------------
__global__ void fill_pool_cols_kernel() {
    int m = blockIdx.x;
    int t = threadIdx.x;
    int b = m >> 8, l = m & 255;
    int h = l >> 4, w = l & 15;
    int si = t >> 7, d = t & 127;
    float v;
    if (si == 0) {
        v = g_y0[b * DIM + d];
    } else {
        int sdim = (si == 1) ? 5 : (si == 2) ? 9 : 13;
        int base = (si == 1) ? POOL5_OFF : (si == 2) ? POOL9_OFF : POOL13_OFF;
        float sh = (h + 0.5f) * (float)sdim / 16.0f - 0.5f;
        sh = fminf(fmaxf(sh, 0.f), (float)sdim - 1.f);
        int h0 = (int)sh;
        int h1 = min(h0 + 1, sdim - 1);
        float fh = sh - (float)h0;
        float sw = (w + 0.5f) * (float)sdim / 16.0f - 0.5f;
        sw = fminf(fmaxf(sw, 0.f), (float)sdim - 1.f);
        int w0 = (int)sw;
        int w1 = min(w0 + 1, sdim - 1);
        float fw = sw - (float)w0;
        const float* Y = g_ys + (size_t)(base + b * sdim * sdim) * DIM;
        float v00 = Y[(size_t)(h0 * sdim + w0) * DIM + d];
        float v01 = Y[(size_t)(h0 * sdim + w1) * DIM + d];
        float v10 = Y[(size_t)(h1 * sdim + w0) * DIM + d];
        float v11 = Y[(size_t)(h1 * sdim + w1) * DIM + d];
        v = (1.f - fh) * ((1.f - fw) * v00 + fw * v01)
          +        fh  * ((1.f - fw) * v10 + fw * v11);
    }
    g_seq[(size_t)m * D_MODEL + COMB + t] = v;
}

// ----------------------------------------------------------------------------
__global__ void conv1d_silu_kernel(const float* __restrict__ w,
                                   const float* __restrict__ bias) {
    int d = blockIdx.x * 256 + threadIdx.x;
    int m = blockIdx.y;
    if (d >= D_INNER) return;
    int b = m >> 8, l = m & 255;
    float acc = bias[d];
    #pragma unroll
    for (int k = 0; k < D_CONV; k++) {
        int ls = l + k - (D_CONV - 1);
        if (ls >= 0)
            acc += w[d * D_CONV + k] * g_xz[((size_t)(b * L_SEQ + ls)) * (2 * D_INNER) + d];
    }
    float sg = 1.f / (1.f + __expf(-acc));
    g_uact[(size_t)m * D_INNER + d] = acc * sg;
}

// ----------------------------------------------------------------------------
__global__ __launch_bounds__(256)
void scan_kernel(const float* __restrict__ A_log, const float* __restrict__ Dp) {
    __shared__ float sB[L_SEQ][D_STATE];
    __shared__ float sC[L_SEQ][D_STATE];
    int b = blockIdx.y;
    int d = blockIdx.x * 256 + threadIdx.x;
    int tid = threadIdx.x;
    for (int i = tid; i < L_SEQ * D_STATE; i += 256) {
        int l = i >> 4, n = i & 15;
        const float* row = g_dbl + (size_t)(b * L_SEQ + l) * XPROJ_LD;
        sB[l][n] = row[DT_RANK + n];
        sC[l][n] = row[DT_RANK + D_STATE + n];
    }
    __syncthreads();
    if (d >= D_INNER) return;

    float Ad[D_STATE];
    #pragma unroll
    for (int n = 0; n < D_STATE; n++) Ad[n] = -expf(A_log[d * D_STATE + n]);
    float Dd = Dp[d];
    float h[D_STATE];
    #pragma unroll
    for (int n = 0; n < D_STATE; n++) h[n] = 0.f;

    for (int l = 0; l < L_SEQ; l++) {
        size_t m = (size_t)(b * L_SEQ + l);
        float dt = g_dt[m * D_INNER + d];
        float u  = g_uact[m * D_INNER + d];
        float z  = g_xz[m * (2 * D_INNER) + D_INNER + d];
        float dtu = dt * u;
        float y = 0.f;
        #pragma unroll
        for (int n = 0; n < D_STATE; n++) {
            float dA = __expf(dt * Ad[n]);
            h[n] = dA * h[n] + dtu * sB[l][n];
            y = fmaf(h[n], sC[l][n], y);
        }
        float sig = 1.f / (1.f + __expf(-z));
        g_y[m * D_INNER + d] = (y + u * Dd) * (z * sig);
    }
}

// ----------------------------------------------------------------------------
extern "C" void kernel_launch(void* const* d_in, const int* in_sizes, int n_in,
                              void* d_out, int out_size) {
    const float* x          = (const float*)d_in[0];
    const float* pc_emb     = (const float*)d_in[1];
    const float* conv_w     = (const float*)d_in[2];
    const float* bn_gamma   = (const float*)d_in[3];
    const float* bn_beta    = (const float*)d_in[4];
    const float* bn_mean    = (const float*)d_in[5];
    const float* bn_var     = (const float*)d_in[6];
    const float* in_proj_w  = (const float*)d_in[7];
    const float* conv1d_w   = (const float*)d_in[8];
    const float* conv1d_b   = (const float*)d_in[9];
    const float* x_proj_w   = (const float*)d_in[10];
    const float* dt_proj_w  = (const float*)d_in[11];
    const float* dt_proj_b  = (const float*)d_in[12];
    const float* A_log      = (const float*)d_in[13];
    const float* Dp         = (const float*)d_in[14];
    const float* out_proj_w = (const float*)d_in[15];
    float* out = (float*)d_out;

    float *p_seq, *p_xz, *p_uact, *p_dbl, *p_dt, *p_y, *p_p0, *p_pooled, *p_ys;
    float *p_bninv, *p_bnbias;
    cudaGetSymbolAddress((void**)&p_seq,    g_seq);
    cudaGetSymbolAddress((void**)&p_xz,     g_xz);
    cudaGetSymbolAddress((void**)&p_uact,   g_uact);
    cudaGetSymbolAddress((void**)&p_dbl,    g_dbl);
    cudaGetSymbolAddress((void**)&p_dt,     g_dt);
    cudaGetSymbolAddress((void**)&p_y,      g_y);
    cudaGetSymbolAddress((void**)&p_p0,     g_p0);
    cudaGetSymbolAddress((void**)&p_pooled, g_pooled);
    cudaGetSymbolAddress((void**)&p_ys,     g_ys);
    cudaGetSymbolAddress((void**)&p_bninv,  g_bninv);
    cudaGetSymbolAddress((void**)&p_bnbias, g_bnbias);

    // 1) BN fold
    prep_bn_kernel<<<2, 256>>>(bn_gamma, bn_beta, bn_mean, bn_var);

    // 2) build comb (both layouts)
    {
        size_t total = (size_t)BATCH * COMB * L_SEQ;
        build_comb_kernel<<<(unsigned)((total + 255) / 256), 256>>>(x, pc_emb);
    }

    // 3) adaptive pools for scales 5/9/13
    pool_avg_kernel<<<dim3(25, BATCH), 256>>>();

    // 4) conv0 full-res (HMMA, BN+ReLU6)
    mma_gemm_kernel<4><<<dim3(1, M_TOTAL / 128), 256>>>(
        p_seq, D_MODEL, conv_w, COMB, p_p0, DIM,
        M_TOTAL, DIM, COMB, p_bninv, p_bnbias);

    // 5) pool0 mean
    pool0_mean_kernel<<<BATCH, DIM>>>();

    // 6) pooled-branch convs (HMMA, BN+ReLU6)
    {
        const int sM[3]   = {1600, 5184, 10816};
        const int sOff[3] = {POOL5_OFF, POOL9_OFF, POOL13_OFF};
        for (int i = 0; i < 3; i++) {
            int pool = i + 1;
            mma_gemm_kernel<4><<<dim3(1, (sM[i] + 127) / 128), 256>>>(
                p_pooled + (size_t)sOff[i] * COMB, COMB,
                conv_w + (size_t)pool * DIM * COMB, COMB,
                p_ys + (size_t)sOff[i] * DIM, DIM,
                sM[i], DIM, COMB,
                p_bninv + pool * DIM, p_bnbias + pool * DIM);
        }
    }

    // 7) fill pool columns of seq
    fill_pool_cols_kernel<<<M_TOTAL, 512>>>();

    // 8) in_proj (HMMA) -> g_xz
    mma_gemm_kernel<0><<<dim3((2 * D_INNER + 127) / 128, M_TOTAL / 128), 256>>>(
        p_seq, D_MODEL, in_proj_w, D_MODEL, p_xz, 2 * D_INNER,
        M_TOTAL, 2 * D_INNER, D_MODEL, nullptr, nullptr);

    // 9) depthwise causal conv1d + SiLU
    conv1d_silu_kernel<<<dim3((D_INNER + 255) / 256, M_TOTAL), 256>>>(conv1d_w, conv1d_b);

    // 10) x_proj (HMMA) -> g_dbl (padded ldc)
    mma_gemm_kernel<0><<<dim3(1, M_TOTAL / 128), 256>>>(
        p_uact, D_INNER, x_proj_w, D_INNER, p_dbl, XPROJ_LD,
        M_TOTAL, XPROJ_N, D_INNER, nullptr, nullptr);

    // 11) dt_proj (HMMA, softplus) -> g_dt   (A = first 81 cols of g_dbl)
    mma_gemm_kernel<3><<<dim3((D_INNER + 127) / 128, M_TOTAL / 128), 256>>>(
        p_dbl, XPROJ_LD, dt_proj_w, DT_RANK, p_dt, D_INNER,
        M_TOTAL, D_INNER, DT_RANK, nullptr, dt_proj_b);

    // 12) selective scan (fused output gate)
    scan_kernel<<<dim3((D_INNER + 255) / 256, BATCH), 256>>>(A_log, Dp);

    // 13) out_proj (HMMA, fused transpose) -> out
    mma_gemm_kernel<1><<<dim3((D_MODEL + 127) / 128, M_TOTAL / 128), 256>>>(
        p_y, D_INNER, out_proj_w, D_INNER, out, 0,
        M_TOTAL, D_MODEL, D_INNER, nullptr, nullptr);
}

// round 11
// speedup vs baseline: 1.2967x; 1.1343x over previous
#include <cuda_runtime.h>
#include <cuda_bf16.h>
#include <cstdint>

// ----------------------------------------------------------------------------
// Problem constants
// ----------------------------------------------------------------------------
#define BATCH     64
#define L_SEQ     256
#define IN_IMG    512
#define IN_PC     256
#define COMB      770
#define DIM       128
#define D_MODEL   1282
#define D_INNER   2564
#define D_STATE   16
#define D_CONV    4
#define DT_RANK   81
#define XPROJ_N   113
#define XPROJ_LD  116            // padded leading dim of g_dbl (even, 8B rows)
#define M_TOTAL   (BATCH * L_SEQ)      // 16384

#define POOL5_OFF   0
#define POOL9_OFF   1600
#define POOL13_OFF  6784
#define POOL_ROWS   17600

// padded weight dims (rows -> mult of 128 per-GEMM need, K -> mult of 32, mult 8 rows ok)
#define W1_ROWS  5248
#define W1_K     1312
#define W2_ROWS  1408
#define W2_K     2592
#define WX_ROWS  128
#define WX_K     2592
#define WD_ROWS  2688
#define WD_K     96
#define WC_ROWS  512
#define WC_K     800

// ----------------------------------------------------------------------------
// Device scratch (static)
// ----------------------------------------------------------------------------
__device__ __align__(16) float g_seq   [(size_t)M_TOTAL * D_MODEL];
__device__ __align__(16) float g_comb  [(size_t)BATCH * COMB * L_SEQ];
__device__ __align__(16) float g_xz    [(size_t)M_TOTAL * 2 * D_INNER];
__device__ __align__(16) float g_uact  [(size_t)M_TOTAL * D_INNER];
__device__ __align__(16) float g_dbl   [(size_t)M_TOTAL * XPROJ_LD];
__device__ __align__(16) float g_dt    [(size_t)M_TOTAL * D_INNER];
__device__ __align__(16) float g_y     [(size_t)M_TOTAL * D_INNER];
__device__ __align__(16) float g_p0    [(size_t)M_TOTAL * DIM];
__device__ __align__(16) float g_y0    [BATCH * DIM];
__device__ __align__(16) float g_pooled[(size_t)POOL_ROWS * COMB];
__device__ __align__(16) float g_ys    [(size_t)POOL_ROWS * DIM];
__device__ __align__(16) float g_bninv [4 * DIM];
__device__ __align__(16) float g_bnbias[4 * DIM];

// pre-split bf16 weight buffers (hi/lo), zero-padded rows and K
__device__ __align__(256) __nv_bfloat16 g_w1h[(size_t)W1_ROWS * W1_K];
__device__ __align__(256) __nv_bfloat16 g_w1l[(size_t)W1_ROWS * W1_K];
__device__ __align__(256) __nv_bfloat16 g_w2h[(size_t)W2_ROWS * W2_K];
__device__ __align__(256) __nv_bfloat16 g_w2l[(size_t)W2_ROWS * W2_K];
__device__ __align__(256) __nv_bfloat16 g_wxh[(size_t)WX_ROWS * WX_K];
__device__ __align__(256) __nv_bfloat16 g_wxl[(size_t)WX_ROWS * WX_K];
__device__ __align__(256) __nv_bfloat16 g_wdh[(size_t)WD_ROWS * WD_K];
__device__ __align__(256) __nv_bfloat16 g_wdl[(size_t)WD_ROWS * WD_K];
__device__ __align__(256) __nv_bfloat16 g_wch[(size_t)WC_ROWS * WC_K];
__device__ __align__(256) __nv_bfloat16 g_wcl[(size_t)WC_ROWS * WC_K];

// ----------------------------------------------------------------------------
// PTX helpers (baseline-ISA only: ldmatrix + mma.sync)
// ----------------------------------------------------------------------------
__device__ __forceinline__ uint32_t smem_to_u32(const void* p) {
    uint32_t a;
    asm("{ .reg .u64 t; cvta.to.shared.u64 t, %1; cvt.u32.u64 %0, t; }"
        : "=r"(a) : "l"(p));
    return a;
}
__device__ __forceinline__ void ldsm4(uint32_t* f, uint32_t addr) {
    asm volatile("ldmatrix.sync.aligned.m8n8.x4.shared.b16 {%0,%1,%2,%3}, [%4];"
                 : "=r"(f[0]), "=r"(f[1]), "=r"(f[2]), "=r"(f[3]) : "r"(addr));
}
__device__ __forceinline__ void mma16816(float* d, const uint32_t* a,
                                         uint32_t b0, uint32_t b1) {
    asm volatile(
        "mma.sync.aligned.m16n8k16.row.col.f32.bf16.bf16.f32 "
        "{%0,%1,%2,%3}, {%4,%5,%6,%7}, {%8,%9}, {%0,%1,%2,%3};"
        : "+f"(d[0]), "+f"(d[1]), "+f"(d[2]), "+f"(d[3])
        : "r"(a[0]), "r"(a[1]), "r"(a[2]), "r"(a[3]), "r"(b0), "r"(b1));
}

// fp32[8] -> bf16 hi uint4 + bf16 lo uint4
__device__ __forceinline__ void cvt_hilo(const float* v, uint4& hi, uint4& lo) {
    uint32_t h[4], l[4];
    #pragma unroll
    for (int i = 0; i < 4; i++) {
        __nv_bfloat16 h0 = __float2bfloat16(v[2*i]);
        __nv_bfloat16 h1 = __float2bfloat16(v[2*i+1]);
        float r0 = v[2*i]   - __bfloat162float(h0);
        float r1 = v[2*i+1] - __bfloat162float(h1);
        __nv_bfloat16 l0 = __float2bfloat16(r0);
        __nv_bfloat16 l1 = __float2bfloat16(r1);
        h[i] = (uint32_t)__bfloat16_as_ushort(h0) | ((uint32_t)__bfloat16_as_ushort(h1) << 16);
        l[i] = (uint32_t)__bfloat16_as_ushort(l0) | ((uint32_t)__bfloat16_as_ushort(l1) << 16);
    }
    hi = make_uint4(h[0], h[1], h[2], h[3]);
    lo = make_uint4(l[0], l[1], l[2], l[3]);
}

// 8-float unit load: vectorized float2 x4 fast path when fully in-bounds and
// 8B-aligned rows; guarded scalar path otherwise.
__device__ __forceinline__ void load_unit(const float* p, bool rowok, int krem,
                                          bool al8, float* v) {
    if (rowok && al8 && krem >= 8) {
        const float2* q = (const float2*)p;
        float2 a = q[0], b = q[1], c = q[2], d = q[3];
        v[0] = a.x; v[1] = a.y; v[2] = b.x; v[3] = b.y;
        v[4] = c.x; v[5] = c.y; v[6] = d.x; v[7] = d.y;
    } else {
        #pragma unroll
        for (int i = 0; i < 8; i++)
            v[i] = (rowok && i < krem) ? p[i] : 0.f;
    }
}

// ----------------------------------------------------------------------------
// fp32 -> bf16 hi/lo split with zero padding (weights, once per replay)
// ----------------------------------------------------------------------------
__global__ void split_kernel(const float* __restrict__ src, int R, int K,
                             __nv_bfloat16* __restrict__ hi,
                             __nv_bfloat16* __restrict__ lo,
                             int Rpad, int Kpad) {
    size_t idx = (size_t)blockIdx.x * 256 + threadIdx.x;
    if (idx >= (size_t)Rpad * Kpad) return;
    int k = (int)(idx % Kpad);
    int r = (int)(idx / Kpad);
    float v = (r < R && k < K) ? src[(size_t)r * K + k] : 0.f;
    __nv_bfloat16 h = __float2bfloat16(v);
    hi[idx] = h;
    lo[idx] = __float2bfloat16(v - __bfloat162float(h));
}

// ----------------------------------------------------------------------------
// HMMA bf16x3-split GEMM.  A fp32 (in-register split), B pre-split bf16 hi/lo
// (rows & K zero-padded: unconditional vector loads, no conversion).
//   C[m,n] = sum_k A[m,k] * B[n,k]
// CTA 128x128, 8 warps (2m x 4n), warp 64x32, K-chunk 32, single-stage smem.
// EPI 0: plain fp32      EPI 1: transposed (b,c,l) final output
// EPI 3: softplus(v+eb[n])      EPI 4: BN+ReLU6
// ----------------------------------------------------------------------------
#define SOFF_AH 0
#define SOFF_AL 8192
#define SOFF_BH 16384
#define SOFF_BL 24576

template <int EPI>
__global__ __launch_bounds__(256)
void mma_gemm_kernel(const float* __restrict__ A, int lda,
                     const __nv_bfloat16* __restrict__ Bh,
                     const __nv_bfloat16* __restrict__ Bl, int ldb,
                     float* __restrict__ C, int ldc,
                     int M, int N, int K, int Kp,
                     const float* __restrict__ ea, const float* __restrict__ eb) {
    __shared__ __align__(16) unsigned char smem_buf[34048];
    const uint32_t sbase = smem_to_u32(smem_buf);
    const int tid = threadIdx.x;
    const int lane = tid & 31, wid = tid >> 5;
    const int wm = wid >> 2, wn = wid & 3;
    const int bm = blockIdx.y * 128, bn = blockIdx.x * 128;
    const int nchunks = Kp / 32;
    const bool alA = ((lda & 1) == 0);

    float acc[4][4][4];
    #pragma unroll
    for (int i = 0; i < 4; i++)
        #pragma unroll
        for (int j = 0; j < 4; j++)
            #pragma unroll
            for (int q = 0; q < 4; q++) acc[i][j][q] = 0.f;

    const int lrow = lane & 15;     // ldmatrix row within 16-row tile
    const int lkh  = lane >> 4;     // k-half select

    for (int ch = 0; ch < nchunks; ch++) {
        const int k0 = ch * 32;
        // ---- stage chunk: A fp32->split, B bf16 direct ----
        #pragma unroll
        for (int uu = 0; uu < 2; uu++) {
            int u = tid + uu * 256;
            int r = u >> 2, cu = u & 3;
            uint32_t soff = (uint32_t)(r * 64 + ((cu ^ ((r >> 1) & 3)) << 4));
            int gk = k0 + cu * 8;
            float va[8];
            load_unit(A + (size_t)(bm + r) * lda + gk, (bm + r) < M, K - gk, alA, va);
            uint4 hi, lo;
            cvt_hilo(va, hi, lo);
            *(uint4*)(smem_buf + SOFF_AH + soff) = hi;
            *(uint4*)(smem_buf + SOFF_AL + soff) = lo;
            size_t gob = (size_t)(bn + r) * ldb + gk;
            *(uint4*)(smem_buf + SOFF_BH + soff) = *(const uint4*)(Bh + gob);
            *(uint4*)(smem_buf + SOFF_BL + soff) = *(const uint4*)(Bl + gob);
        }
        __syncthreads();
        // ---- mma over the 32-K chunk (two k16 steps) ----
        #pragma unroll
        for (int k16 = 0; k16 < 2; k16++) {
            const int cbase = k16 * 2 + lkh;
            uint32_t ahf[4][4], alf[4][4], bhf[4][2], blf[4][2];
            #pragma unroll
            for (int mi = 0; mi < 4; mi++) {
                int r = wm * 64 + mi * 16 + lrow;
                uint32_t off = (uint32_t)(r * 64 + ((cbase ^ ((r >> 1) & 3)) << 4));
                ldsm4(ahf[mi], sbase + SOFF_AH + off);
                ldsm4(alf[mi], sbase + SOFF_AL + off);
            }
            #pragma unroll
            for (int ni = 0; ni < 2; ni++) {
                int r = wn * 32 + ni * 16 + lrow;
                uint32_t off = (uint32_t)(r * 64 + ((cbase ^ ((r >> 1) & 3)) << 4));
                uint32_t bt[4];
                ldsm4(bt, sbase + SOFF_BH + off);
                bhf[ni * 2 + 0][0] = bt[0]; bhf[ni * 2 + 0][1] = bt[2];
                bhf[ni * 2 + 1][0] = bt[1]; bhf[ni * 2 + 1][1] = bt[3];
                ldsm4(bt, sbase + SOFF_BL + off);
                blf[ni * 2 + 0][0] = bt[0]; blf[ni * 2 + 0][1] = bt[2];
                blf[ni * 2 + 1][0] = bt[1]; blf[ni * 2 + 1][1] = bt[3];
            }
            #pragma unroll
            for (int mi = 0; mi < 4; mi++)
                #pragma unroll
                for (int nj = 0; nj < 4; nj++) {
                    mma16816(acc[mi][nj], ahf[mi], bhf[nj][0], bhf[nj][1]);
                    mma16816(acc[mi][nj], ahf[mi], blf[nj][0], blf[nj][1]);
                    mma16816(acc[mi][nj], alf[mi], bhf[nj][0], bhf[nj][1]);
                }
        }
        __syncthreads();
    }

    // ---- epilogue: two passes (warps wm==0 then wm==1) reusing tile smem ----
    const int m0 = bm + wm * 64, n0 = bn + wn * 32;
    const int tr = lane >> 2, tc2 = (lane & 3) * 2;
    #pragma unroll
    for (int pass = 0; pass < 2; pass++) {
        __syncthreads();
        if (wm == pass) {
            float* tp = (float*)(smem_buf + (size_t)wn * 8448);   // 64x33 floats
            #pragma unroll
            for (int mi = 0; mi < 4; mi++)
                #pragma unroll
                for (int nj = 0; nj < 4; nj++) {
                    int r0 = mi * 16 + tr, c0 = nj * 8 + tc2;
                    tp[r0 * 33 + c0]           = acc[mi][nj][0];
                    tp[r0 * 33 + c0 + 1]       = acc[mi][nj][1];
                    tp[(r0 + 8) * 33 + c0]     = acc[mi][nj][2];
                    tp[(r0 + 8) * 33 + c0 + 1] = acc[mi][nj][3];
                }
            __syncwarp();
            if (EPI == 0) {
                int gn = n0 + lane;
                if (gn < N)
                    for (int r = 0; r < 64; r++) {
                        int gm = m0 + r;
                        if (gm < M) C[(size_t)gm * ldc + gn] = tp[r * 33 + lane];
                    }
            } else if (EPI == 3) {
                int gn = n0 + lane;
                if (gn < N) {
                    float bias = eb[gn];
                    for (int r = 0; r < 64; r++) {
                        int gm = m0 + r;
                        if (gm >= M) break;
                        float v = tp[r * 33 + lane] + bias;
                        v = (v > 20.f) ? v : log1pf(expf(v));
                        C[(size_t)gm * ldc + gn] = v;
                    }
                }
            } else if (EPI == 4) {
                int gn = n0 + lane;
                if (gn < N) {
                    float sa = ea[gn], sb = eb[gn];
                    for (int r = 0; r < 64; r++) {
                        int gm = m0 + r;
                        if (gm >= M) break;
                        float v = tp[r * 33 + lane] * sa + sb;
                        v = fminf(fmaxf(v, 0.f), 6.f);
                        C[(size_t)gm * ldc + gn] = v;
                    }
                }
            } else {  // EPI 1: transposed final output (b, c, l); M == 16384
                for (int c = 0; c < 32; c++) {
                    int gn = n0 + c;
                    if (gn >= N) break;
                    int m = m0 + lane;
                    int b = m >> 8, l = m & 255;
                    C[((size_t)(b * D_MODEL + gn)) * L_SEQ + l] = tp[lane * 33 + c];
                    m = m0 + 32 + lane;
                    b = m >> 8; l = m & 255;
                    C[((size_t)(b * D_MODEL + gn)) * L_SEQ + l] = tp[(lane + 32) * 33 + c];
                }
            }
        }
    }
}

// ----------------------------------------------------------------------------
__global__ void prep_bn_kernel(const float* __restrict__ gamma,
                               const float* __restrict__ beta,
                               const float* __restrict__ mean,
                               const float* __restrict__ var) {
    int i = blockIdx.x * 256 + threadIdx.x;
    if (i < 4 * DIM) {
        float iv = rsqrtf(var[i] + 1e-5f) * gamma[i];
        g_bninv[i]  = iv;
        g_bnbias[i] = beta[i] - mean[i] * iv;
    }
}

// ----------------------------------------------------------------------------
__global__ void build_comb_kernel(const float* __restrict__ x,
                                  const float* __restrict__ pc) {
    size_t idx = (size_t)blockIdx.x * 256 + threadIdx.x;
    if (idx >= (size_t)BATCH * COMB * L_SEQ) return;
    int l = (int)(idx % L_SEQ);
    int c = (int)((idx / L_SEQ) % COMB);
    int b = (int)(idx / ((size_t)L_SEQ * COMB));
    float v;
    if (c < IN_IMG) {
        v = x[((size_t)(b * IN_IMG + c)) * L_SEQ + l];
    } else if (c == IN_IMG) {
        int w = l & 15;
        v = -0.3f + 0.6f * (float)w / 15.0f;
    } else if (c == IN_IMG + 1) {
        int h = l >> 4;
        v = -0.3f + 0.6f * (float)h / 15.0f;
    } else {
        v = pc[b * IN_PC + (c - IN_IMG - 2)];
    }
    g_comb[((size_t)(b * COMB + c)) * L_SEQ + l] = v;
    g_seq[((size_t)(b * L_SEQ + l)) * D_MODEL + c] = v;
}

// ----------------------------------------------------------------------------
__global__ void pool_avg_kernel() {
    __shared__ float s[32][257];
    int b  = blockIdx.y;
    int c0 = blockIdx.x * 32;
    int tid = threadIdx.x;
    for (int i = tid; i < 32 * 256; i += 256) {
        int cl = i >> 8, l = i & 255;
        int c = c0 + cl;
        s[cl][l] = (c < COMB) ? g_comb[((size_t)(b * COMB + c)) * L_SEQ + l] : 0.f;
    }
    __syncthreads();
    for (int oidx = tid; oidx < 275 * 32; oidx += 256) {
        int cl = oidx & 31;
        int q  = oidx >> 5;
        int sdim, qb, base;
        if (q < 25)       { sdim = 5;  qb = q;       base = POOL5_OFF;  }
        else if (q < 106) { sdim = 9;  qb = q - 25;  base = POOL9_OFF;  }
        else              { sdim = 13; qb = q - 106; base = POOL13_OFF; }
        int o = qb / sdim, p = qb % sdim;
        int h0 = (o * 16) / sdim, h1 = ((o + 1) * 16 + sdim - 1) / sdim;
        int w0 = (p * 16) / sdim, w1 = ((p + 1) * 16 + sdim - 1) / sdim;
        float sum = 0.f;
        for (int h = h0; h < h1; h++)
            for (int w = w0; w < w1; w++)
                sum += s[cl][h * 16 + w];
        sum *= 1.0f / (float)((h1 - h0) * (w1 - w0));
        int c = c0 + cl;
        if (c < COMB)
            g_pooled[((size_t)(base + b * sdim * sdim + qb)) * COMB + c] = sum;
    }
}

// ----------------------------------------------------------------------------
__global__ void pool0_mean_kernel() {
    int b = blockIdx.x;
    int d = threadIdx.x;
    float s = 0.f;
    for (int l = 0; l < L_SEQ; l++)
        s += g_p0[((size_t)(b * L_SEQ + l)) * DIM + d];
    g_y0[b * DIM + d] = s * (1.0f / (float)L_SEQ);
}

// ----------------------------------------------------------------------------
__global__ void fill_pool_cols_kernel() {
    int m = blockIdx.x;
    int t = threadIdx.x;
    int b = m >> 8, l = m & 255;
    int h = l >> 4, w = l & 15;
    int si = t >> 7, d = t & 127;
    float v;
    if (si == 0) {
        v = g_y0[b * DIM + d];
    } else {
        int sdim = (si == 1) ? 5 : (si == 2) ? 9 : 13;
        int base = (si == 1) ? POOL5_OFF : (si == 2) ? POOL9_OFF : POOL13_OFF;
        float sh = (h + 0.5f) * (float)sdim / 16.0f - 0.5f;
        sh = fminf(fmaxf(sh, 0.f), (float)sdim - 1.f);
        int h0 = (int)sh;
        int h1 = min(h0 + 1, sdim - 1);
        float fh = sh - (float)h0;
        float sw = (w + 0.5f) * (float)sdim / 16.0f - 0.5f;
        sw = fminf(fmaxf(sw, 0.f), (float)sdim - 1.f);
        int w0 = (int)sw;
        int w1 = min(w0 + 1, sdim - 1);
        float fw = sw - (float)w0;
        const float* Y = g_ys + (size_t)(base + b * sdim * sdim) * DIM;
        float v00 = Y[(size_t)(h0 * sdim + w0) * DIM + d];
        float v01 = Y[(size_t)(h0 * sdim + w1) * DIM + d];
        float v10 = Y[(size_t)(h1 * sdim + w0) * DIM + d];
        float v11 = Y[(size_t)(h1 * sdim + w1) * DIM + d];
        v = (1.f - fh) * ((1.f - fw) * v00 + fw * v01)
          +        fh  * ((1.f - fw) * v10 + fw * v11);
    }
    g_seq[(size_t)m * D_MODEL + COMB + t] = v;
}

// ----------------------------------------------------------------------------
__global__ void conv1d_silu_kernel(const float* __restrict__ w,
                                   const float* __restrict__ bias) {
    int d = blockIdx.x * 256 + threadIdx.x;
    int m = blockIdx.y;
    if (d >= D_INNER) return;
    int b = m >> 8, l = m & 255;
    float acc = bias[d];
    #pragma unroll
    for (int k = 0; k < D_CONV; k++) {
        int ls = l + k - (D_CONV - 1);
        if (ls >= 0)
            acc += w[d * D_CONV + k] * g_xz[((size_t)(b * L_SEQ + ls)) * (2 * D_INNER) + d];
    }
    float sg = 1.f / (1.f + __expf(-acc));
    g_uact[(size_t)m * D_INNER + d] = acc * sg;
}

// ----------------------------------------------------------------------------
__global__ __launch_bounds__(256)
void scan_kernel(const float* __restrict__ A_log, const float* __restrict__ Dp) {
    __shared__ float sB[L_SEQ][D_STATE];
    __shared__ float sC[L_SEQ][D_STATE];
    int b = blockIdx.y;
    int d = blockIdx.x * 256 + threadIdx.x;
    int tid = threadIdx.x;
    for (int i = tid; i < L_SEQ * D_STATE; i += 256) {
        int l = i >> 4, n = i & 15;
        const float* row = g_dbl + (size_t)(b * L_SEQ + l) * XPROJ_LD;
        sB[l][n] = row[DT_RANK + n];
        sC[l][n] = row[DT_RANK + D_STATE + n];
    }
    __syncthreads();
    if (d >= D_INNER) return;

    float Ad[D_STATE];
    #pragma unroll
    for (int n = 0; n < D_STATE; n++) Ad[n] = -expf(A_log[d * D_STATE + n]);
    float Dd = Dp[d];
    float h[D_STATE];
    #pragma unroll
    for (int n = 0; n < D_STATE; n++) h[n] = 0.f;

    for (int l = 0; l < L_SEQ; l++) {
        size_t m = (size_t)(b * L_SEQ + l);
        float dt = g_dt[m * D_INNER + d];
        float u  = g_uact[m * D_INNER + d];
        float z  = g_xz[m * (2 * D_INNER) + D_INNER + d];
        float dtu = dt * u;
        float y = 0.f;
        #pragma unroll
        for (int n = 0; n < D_STATE; n++) {
            float dA = __expf(dt * Ad[n]);
            h[n] = dA * h[n] + dtu * sB[l][n];
            y = fmaf(h[n], sC[l][n], y);
        }
        float sig = 1.f / (1.f + __expf(-z));
        g_y[m * D_INNER + d] = (y + u * Dd) * (z * sig);
    }
}

// ----------------------------------------------------------------------------
extern "C" void kernel_launch(void* const* d_in, const int* in_sizes, int n_in,
                              void* d_out, int out_size) {
    const float* x          = (const float*)d_in[0];
    const float* pc_emb     = (const float*)d_in[1];
    const float* conv_w     = (const float*)d_in[2];
    const float* bn_gamma   = (const float*)d_in[3];
    const float* bn_beta    = (const float*)d_in[4];
    const float* bn_mean    = (const float*)d_in[5];
    const float* bn_var     = (const float*)d_in[6];
    const float* in_proj_w  = (const float*)d_in[7];
    const float* conv1d_w   = (const float*)d_in[8];
    const float* conv1d_b   = (const float*)d_in[9];
    const float* x_proj_w   = (const float*)d_in[10];
    const float* dt_proj_w  = (const float*)d_in[11];
    const float* dt_proj_b  = (const float*)d_in[12];
    const float* A_log      = (const float*)d_in[13];
    const float* Dp         = (const float*)d_in[14];
    const float* out_proj_w = (const float*)d_in[15];
    float* out = (float*)d_out;

    float *p_seq, *p_xz, *p_uact, *p_dbl, *p_dt, *p_y, *p_p0, *p_pooled, *p_ys;
    float *p_bninv, *p_bnbias;
    __nv_bfloat16 *p_w1h, *p_w1l, *p_w2h, *p_w2l, *p_wxh, *p_wxl, *p_wdh, *p_wdl, *p_wch, *p_wcl;
    cudaGetSymbolAddress((void**)&p_seq,    g_seq);
    cudaGetSymbolAddress((void**)&p_xz,     g_xz);
    cudaGetSymbolAddress((void**)&p_uact,   g_uact);
    cudaGetSymbolAddress((void**)&p_dbl,    g_dbl);
    cudaGetSymbolAddress((void**)&p_dt,     g_dt);
    cudaGetSymbolAddress((void**)&p_y,      g_y);
    cudaGetSymbolAddress((void**)&p_p0,     g_p0);
    cudaGetSymbolAddress((void**)&p_pooled, g_pooled);
    cudaGetSymbolAddress((void**)&p_ys,     g_ys);
    cudaGetSymbolAddress((void**)&p_bninv,  g_bninv);
    cudaGetSymbolAddress((void**)&p_bnbias, g_bnbias);
    cudaGetSymbolAddress((void**)&p_w1h, g_w1h);  cudaGetSymbolAddress((void**)&p_w1l, g_w1l);
    cudaGetSymbolAddress((void**)&p_w2h, g_w2h);  cudaGetSymbolAddress((void**)&p_w2l, g_w2l);
    cudaGetSymbolAddress((void**)&p_wxh, g_wxh);  cudaGetSymbolAddress((void**)&p_wxl, g_wxl);
    cudaGetSymbolAddress((void**)&p_wdh, g_wdh);  cudaGetSymbolAddress((void**)&p_wdl, g_wdl);
    cudaGetSymbolAddress((void**)&p_wch, g_wch);  cudaGetSymbolAddress((void**)&p_wcl, g_wcl);

    // 1) BN fold + weight pre-splits
    prep_bn_kernel<<<2, 256>>>(bn_gamma, bn_beta, bn_mean, bn_var);
    {
        size_t n;
        n = (size_t)WC_ROWS * WC_K;
        split_kernel<<<(unsigned)((n + 255) / 256), 256>>>(conv_w, 512, COMB, p_wch, p_wcl, WC_ROWS, WC_K);
        n = (size_t)W1_ROWS * W1_K;
        split_kernel<<<(unsigned)((n + 255) / 256), 256>>>(in_proj_w, 2 * D_INNER, D_MODEL, p_w1h, p_w1l, W1_ROWS, W1_K);
        n = (size_t)WX_ROWS * WX_K;
        split_kernel<<<(unsigned)((n + 255) / 256), 256>>>(x_proj_w, XPROJ_N, D_INNER, p_wxh, p_wxl, WX_ROWS, WX_K);
        n = (size_t)WD_ROWS * WD_K;
        split_kernel<<<(unsigned)((n + 255) / 256), 256>>>(dt_proj_w, D_INNER, DT_RANK, p_wdh, p_wdl, WD_ROWS, WD_K);
        n = (size_t)W2_ROWS * W2_K;
        split_kernel<<<(unsigned)((n + 255) / 256), 256>>>(out_proj_w, D_MODEL, D_INNER, p_w2h, p_w2l, W2_ROWS, W2_K);
    }

    // 2) build comb (both layouts)
    {
        size_t total = (size_t)BATCH * COMB * L_SEQ;
        build_comb_kernel<<<(unsigned)((total + 255) / 256), 256>>>(x, pc_emb);
    }

    // 3) adaptive pools for scales 5/9/13
    pool_avg_kernel<<<dim3(25, BATCH), 256>>>();

    // 4) conv0 full-res (HMMA, BN+ReLU6); W rows 0..127 of padded conv buffer
    mma_gemm_kernel<4><<<dim3(1, M_TOTAL / 128), 256>>>(
        p_seq, D_MODEL, p_wch, p_wcl, WC_K, p_p0, DIM,
        M_TOTAL, DIM, COMB, WC_K, p_bninv, p_bnbias);

    // 5) pool0 mean
    pool0_mean_kernel<<<BATCH, DIM>>>();

    // 6) pooled-branch convs (HMMA, BN+ReLU6)
    {
        const int sM[3]   = {1600, 5184, 10816};
        const int sOff[3] = {POOL5_OFF, POOL9_OFF, POOL13_OFF};
        for (int i = 0; i < 3; i++) {
            int pool = i + 1;
            mma_gemm_kernel<4><<<dim3(1, (sM[i] + 127) / 128), 256>>>(
                p_pooled + (size_t)sOff[i] * COMB, COMB,
                p_wch + (size_t)pool * DIM * WC_K, p_wcl + (size_t)pool * DIM * WC_K, WC_K,
                p_ys + (size_t)sOff[i] * DIM, DIM,
                sM[i], DIM, COMB, WC_K,
                p_bninv + pool * DIM, p_bnbias + pool * DIM);
        }
    }

    // 7) fill pool columns of seq
    fill_pool_cols_kernel<<<M_TOTAL, 512>>>();

    // 8) in_proj (HMMA) -> g_xz
    mma_gemm_kernel<0><<<dim3(W1_ROWS / 128, M_TOTAL / 128), 256>>>(
        p_seq, D_MODEL, p_w1h, p_w1l, W1_K, p_xz, 2 * D_INNER,
        M_TOTAL, 2 * D_INNER, D_MODEL, W1_K, nullptr, nullptr);

    // 9) depthwise causal conv1d + SiLU
    conv1d_silu_kernel<<<dim3((D_INNER + 255) / 256, M_TOTAL), 256>>>(conv1d_w, conv1d_b);

    // 10) x_proj (HMMA) -> g_dbl (padded ldc)
    mma_gemm_kernel<0><<<dim3(1, M_TOTAL / 128), 256>>>(
        p_uact, D_INNER, p_wxh, p_wxl, WX_K, p_dbl, XPROJ_LD,
        M_TOTAL, XPROJ_N, D_INNER, WX_K, nullptr, nullptr);

    // 11) dt_proj (HMMA, softplus) -> g_dt   (A = first 81 cols of g_dbl)
    mma_gemm_kernel<3><<<dim3(WD_ROWS / 128, M_TOTAL / 128), 256>>>(
        p_dbl, XPROJ_LD, p_wdh, p_wdl, WD_K, p_dt, D_INNER,
        M_TOTAL, D_INNER, DT_RANK, WD_K, nullptr, dt_proj_b);

    // 12) selective scan (fused output gate)
    scan_kernel<<<dim3((D_INNER + 255) / 256, BATCH), 256>>>(A_log, Dp);

    // 13) out_proj (HMMA, fused transpose) -> out
    mma_gemm_kernel<1><<<dim3(W2_ROWS / 128, M_TOTAL / 128), 256>>>(
        p_y, D_INNER, p_w2h, p_w2l, W2_K, out, 0,
        M_TOTAL, D_MODEL, D_INNER, W2_K, nullptr, nullptr);
}